// round 8
// baseline (speedup 1.0000x reference)
#include <cuda_runtime.h>
#include <cuda_fp16.h>
#include <cstdint>

#define NPTS 1000000
#define WRES 64
#define NSAMP (NPTS * 12)

// Duplicated-pair grid in fp16: per (scale, ci, y, x) a 64B block
//   { texel(x): 16 ch, texel(min(x+1,63)): 16 ch }
// halfs per scale: 3*H*64*32 = 6144*H -> s0 786432, s1 1572864, s2 3145728, s3 6291456
// offsets: 786432 * (2^s - 1)
__device__ __align__(16) __half g_dup[11796480];

// -------- transpose+convert+duplicate: [3,16,H,64] fp32 -> blocks --------
__global__ void __launch_bounds__(256) transpose_all(const float* __restrict__ g0,
                                                     const float* __restrict__ g1,
                                                     const float* __restrict__ g2,
                                                     const float* __restrict__ g3) {
    int idx = blockIdx.x * blockDim.x + threadIdx.x;
    if (idx >= 368640) return;   // 3*64*(128+256+512+1024)
    const float* g;
    int H, toff, local, hshift;
    if (idx < 24576)       { g = g0; H = 128;  toff = 0;       local = idx;          hshift = 7;  }
    else if (idx < 73728)  { g = g1; H = 256;  toff = 786432;  local = idx - 24576;  hshift = 8;  }
    else if (idx < 172032) { g = g2; H = 512;  toff = 2359296; local = idx - 73728;  hshift = 9;  }
    else                   { g = g3; H = 1024; toff = 5505024; local = idx - 172032; hshift = 10; }

    int w = local & 63;
    int rest = local >> 6;            // ci*H + h
    int h = rest & (H - 1);
    int ci = rest >> hshift;
    const float* src = g + ((size_t)(ci * 16) * H + h) * WRES + w;
    int dx = (w < 63) ? 1 : 0;        // clamp x+1 at edge
    size_t fstride = (size_t)H * WRES;

    float t0[16], t1[16];
#pragma unroll
    for (int f = 0; f < 16; f++) {
        t0[f] = src[f * fstride];
        t1[f] = src[f * fstride + dx];
    }

    __half2 hv[16];
#pragma unroll
    for (int f = 0; f < 8; f++) {
        hv[f]     = __floats2half2_rn(t0[2 * f], t0[2 * f + 1]);
        hv[8 + f] = __floats2half2_rn(t1[2 * f], t1[2 * f + 1]);
    }

    uint4* dst = reinterpret_cast<uint4*>(g_dup + toff + (size_t)local * 32);
    const uint32_t* u = reinterpret_cast<const uint32_t*>(hv);
#pragma unroll
    for (int q = 0; q < 4; q++)
        dst[q] = make_uint4(u[4 * q], u[4 * q + 1], u[4 * q + 2], u[4 * q + 3]);
}

// -------- main sample kernel: 4 lanes per sample, fp32 lerp --------
// lane r in group: bit0 = feature half (16B chunk), bit1 = x-corner.
// Block layout makes each row-load one 64B-aligned region -> 1 line per row.
__global__ void __launch_bounds__(256) sample_k(const float* __restrict__ pts,
                                                const float* __restrict__ radius,
                                                float* __restrict__ out) {
    int t = blockIdx.x * blockDim.x + threadIdx.x;
    int g = t >> 2;               // sample id = n*12 + j
    int r = t & 3;
    int n = g / 12;
    int j = g - n * 12;
    int sIdx = j / 3;             // 0..3
    int ci = j - sIdx * 3;        // 0..2
    int H = 128 << sIdx;

    float xv = __ldg(pts + n * 3 + ci);
    float yv = __ldg(radius + n);

    float fx = (xv + 1.0f) * 31.5f;                 // 0.5*(W-1)
    float fy = (yv + 1.0f) * (0.5f * (float)(H - 1));
    float x0f = floorf(fx);
    float y0f = floorf(fy);
    float wx = fx - x0f;
    float wy = fy - y0f;
    int x0 = min(max((int)x0f, 0), 63);
    int y0 = min(max((int)y0f, 0), H - 1);
    int y1 = min(y0 + 1, H - 1);

    int toff = 786432 * ((1 << sIdx) - 1);
    const __half* tb = g_dup + toff + (size_t)ci * H * 2048;   // 2048 halfs per row

    // lane's 16B within the sample's 64B block: offset r*8 halfs
    const uint4* pA = reinterpret_cast<const uint4*>(tb + ((size_t)(y0 << 6) + x0) * 32 + r * 8);
    const uint4* pB = reinterpret_cast<const uint4*>(tb + ((size_t)(y1 << 6) + x0) * 32 + r * 8);
    uint4 vA = *pA;               // row y0
    uint4 vB = *pB;               // row y1

    float wxr = (r & 2) ? wx : (1.0f - wx);
    float w0 = (1.0f - wy) * wxr;
    float w1 = wy * wxr;

    const __half2* hA = reinterpret_cast<const __half2*>(&vA);
    const __half2* hB = reinterpret_cast<const __half2*>(&vB);
    float acc[8];
#pragma unroll
    for (int k = 0; k < 4; k++) {
        float2 a = __half22float2(hA[k]);
        float2 b = __half22float2(hB[k]);
        acc[2 * k]     = a.x * w0 + b.x * w1;
        acc[2 * k + 1] = a.y * w0 + b.y * w1;
    }

    // combine the two x-corners (lane bit1)
#pragma unroll
    for (int i = 0; i < 8; i++) acc[i] += __shfl_xor_sync(0xffffffffu, acc[i], 2);

    // store one 16B quarter per lane: chunk = (r&1)*2 + (r>>1)
    int chunk = ((r & 1) << 1) | (r >> 1);
    float4 st = (r & 2) ? make_float4(acc[4], acc[5], acc[6], acc[7])
                        : make_float4(acc[0], acc[1], acc[2], acc[3]);
    float4* o = reinterpret_cast<float4*>(out + (size_t)n * 192 + j * 16 + chunk * 4);
    *o = st;
}

extern "C" void kernel_launch(void* const* d_in, const int* in_sizes, int n_in,
                              void* d_out, int out_size) {
    const float* pts    = (const float*)d_in[0];
    const float* radius = (const float*)d_in[1];
    float* out = (float*)d_out;

    transpose_all<<<(368640 + 255) / 256, 256>>>((const float*)d_in[2],
                                                 (const float*)d_in[3],
                                                 (const float*)d_in[4],
                                                 (const float*)d_in[5]);

    // NSAMP*4 = 48,000,000 threads; 256/block -> 187500 blocks exactly
    sample_k<<<187500, 256>>>(pts, radius, out);
}

// round 9
// speedup vs baseline: 1.2780x; 1.2780x over previous
#include <cuda_runtime.h>
#include <cuda_fp16.h>
#include <cstdint>

#define NPTS 1000000
#define WRES 64

// Transposed grids in fp16, layout [3, H, W, 16] per scale, concatenated.
// per-scale half counts: s0 393216, s1 786432, s2 1572864, s3 3145728
__device__ __align__(16) __half g_trans[5898240];

// -------- fused transpose+convert: [3,16,H,64] fp32 -> [3,H,64,16] fp16 --------
__global__ void __launch_bounds__(256) transpose_all(const float* __restrict__ g0,
                                                     const float* __restrict__ g1,
                                                     const float* __restrict__ g2,
                                                     const float* __restrict__ g3) {
    int idx = blockIdx.x * blockDim.x + threadIdx.x;
    if (idx >= 368640) return;   // 3*64*(128+256+512+1024)
    const float* g;
    int H, toff, local, hshift;
    if (idx < 24576)       { g = g0; H = 128;  toff = 0;       local = idx;          hshift = 7;  }
    else if (idx < 73728)  { g = g1; H = 256;  toff = 393216;  local = idx - 24576;  hshift = 8;  }
    else if (idx < 172032) { g = g2; H = 512;  toff = 1179648; local = idx - 73728;  hshift = 9;  }
    else                   { g = g3; H = 1024; toff = 2752512; local = idx - 172032; hshift = 10; }

    int w = local & 63;
    int rest = local >> 6;            // ci*H + h
    int h = rest & (H - 1);
    int ci = rest >> hshift;
    const float* src = g + ((size_t)(ci * 16) * H + h) * WRES + w;
    float tmp[16];
    size_t fstride = (size_t)H * WRES;
#pragma unroll
    for (int f = 0; f < 16; f++) tmp[f] = src[f * fstride];

    __half2 hv[8];
#pragma unroll
    for (int f = 0; f < 8; f++) hv[f] = __floats2half2_rn(tmp[2 * f], tmp[2 * f + 1]);

    uint4* dst = reinterpret_cast<uint4*>(g_trans + toff + (size_t)local * 16);
    uint4 a, b;
    a.x = *(uint32_t*)&hv[0]; a.y = *(uint32_t*)&hv[1];
    a.z = *(uint32_t*)&hv[2]; a.w = *(uint32_t*)&hv[3];
    b.x = *(uint32_t*)&hv[4]; b.y = *(uint32_t*)&hv[5];
    b.z = *(uint32_t*)&hv[6]; b.w = *(uint32_t*)&hv[7];
    dst[0] = a;
    dst[1] = b;
}

// -------- main sample kernel: 4 lanes x 2 samples per thread --------
// Group G = n*6 + jlo handles samples j=jlo (scale sIdx) and j=jlo+6 (scale sIdx+2),
// which share ci (same x coordinate) and radius (y source).
// lane r: bit0 = feature half (16B chunk), bit1 = x-corner.
__global__ void __launch_bounds__(256) sample_k(const float* __restrict__ pts,
                                                const float* __restrict__ radius,
                                                float* __restrict__ out) {
    int t = blockIdx.x * blockDim.x + threadIdx.x;
    int G = t >> 2;               // 6M groups
    int r = t & 3;
    int n = G / 6;
    int jlo = G - n * 6;          // 0..5
    int s0 = jlo / 3;             // 0 or 1
    int ci = jlo - s0 * 3;        // 0..2
    int H0 = 128 << s0;
    int H1 = 512 << s0;           // scale s0+2

    float xv = __ldg(pts + n * 3 + ci);
    float yv = __ldg(radius + n);

    // shared x setup
    float fx = (xv + 1.0f) * 31.5f;
    float x0f = floorf(fx);
    float wx = fx - x0f;
    int x0 = min(max((int)x0f, 0), 63);
    int x1 = min(x0 + 1, 63);
    int xs = (r & 2) ? x1 : x0;
    int hsel = (r & 1) * 8;

    // per-sample y setup
    float fyA = (yv + 1.0f) * (0.5f * (float)(H0 - 1));
    float fyB = (yv + 1.0f) * (0.5f * (float)(H1 - 1));
    float yA0f = floorf(fyA);
    float yB0f = floorf(fyB);
    float wyA = fyA - yA0f;
    float wyB = fyB - yB0f;
    int yA0 = min(max((int)yA0f, 0), H0 - 1);
    int yA1 = min(yA0 + 1, H0 - 1);
    int yB0 = min(max((int)yB0f, 0), H1 - 1);
    int yB1 = min(yB0 + 1, H1 - 1);

    int toffA = 393216 * ((1 << s0) - 1);
    int toffB = 393216 * ((4 << s0) - 1);
    const __half* tA = g_trans + toffA + (size_t)(ci * H0) * (WRES * 16);
    const __half* tB = g_trans + toffB + (size_t)(ci * H1) * (WRES * 16);

    // 4 independent 16B loads -> MLP = 4
    const uint4* pA0 = reinterpret_cast<const uint4*>(tA + (size_t)((yA0 << 6) + xs) * 16 + hsel);
    const uint4* pA1 = reinterpret_cast<const uint4*>(tA + (size_t)((yA1 << 6) + xs) * 16 + hsel);
    const uint4* pB0 = reinterpret_cast<const uint4*>(tB + (size_t)((yB0 << 6) + xs) * 16 + hsel);
    const uint4* pB1 = reinterpret_cast<const uint4*>(tB + (size_t)((yB1 << 6) + xs) * 16 + hsel);
    uint4 vA0 = *pA0;
    uint4 vA1 = *pA1;
    uint4 vB0 = *pB0;
    uint4 vB1 = *pB1;

    float wxr = (r & 2) ? wx : (1.0f - wx);
    float wA0 = (1.0f - wyA) * wxr;
    float wA1 = wyA * wxr;
    float wB0 = (1.0f - wyB) * wxr;
    float wB1 = wyB * wxr;

    const __half2* hA0 = reinterpret_cast<const __half2*>(&vA0);
    const __half2* hA1 = reinterpret_cast<const __half2*>(&vA1);
    const __half2* hB0 = reinterpret_cast<const __half2*>(&vB0);
    const __half2* hB1 = reinterpret_cast<const __half2*>(&vB1);

    float accA[8], accB[8];
#pragma unroll
    for (int k = 0; k < 4; k++) {
        float2 a0 = __half22float2(hA0[k]);
        float2 a1 = __half22float2(hA1[k]);
        accA[2 * k]     = a0.x * wA0 + a1.x * wA1;
        accA[2 * k + 1] = a0.y * wA0 + a1.y * wA1;
        float2 b0 = __half22float2(hB0[k]);
        float2 b1 = __half22float2(hB1[k]);
        accB[2 * k]     = b0.x * wB0 + b1.x * wB1;
        accB[2 * k + 1] = b0.y * wB0 + b1.y * wB1;
    }

    // combine x-corners (lane bit1), both samples
#pragma unroll
    for (int i = 0; i < 8; i++) accA[i] += __shfl_xor_sync(0xffffffffu, accA[i], 2);
#pragma unroll
    for (int i = 0; i < 8; i++) accB[i] += __shfl_xor_sync(0xffffffffu, accB[i], 2);

    // store one 16B quarter per lane per sample: chunk = (r&1)*2 + (r>>1)
    int chunk = ((r & 1) << 1) | (r >> 1);
    float4 stA = (r & 2) ? make_float4(accA[4], accA[5], accA[6], accA[7])
                         : make_float4(accA[0], accA[1], accA[2], accA[3]);
    float4 stB = (r & 2) ? make_float4(accB[4], accB[5], accB[6], accB[7])
                         : make_float4(accB[0], accB[1], accB[2], accB[3]);
    float* obase = out + (size_t)n * 192 + chunk * 4;
    *reinterpret_cast<float4*>(obase + jlo * 16)       = stA;
    *reinterpret_cast<float4*>(obase + (jlo + 6) * 16) = stB;
}

extern "C" void kernel_launch(void* const* d_in, const int* in_sizes, int n_in,
                              void* d_out, int out_size) {
    const float* pts    = (const float*)d_in[0];
    const float* radius = (const float*)d_in[1];
    float* out = (float*)d_out;

    transpose_all<<<(368640 + 255) / 256, 256>>>((const float*)d_in[2],
                                                 (const float*)d_in[3],
                                                 (const float*)d_in[4],
                                                 (const float*)d_in[5]);

    // 6M groups * 4 lanes = 24M threads; 256/block -> 93750 blocks exactly
    sample_k<<<93750, 256>>>(pts, radius, out);
}